// round 1
// baseline (speedup 1.0000x reference)
#include <cuda_runtime.h>
#include <cuda_bf16.h>
#include <math.h>

// ---------------- problem constants ----------------
#define NB   8
#define NS   256
#define NP   16
#define ND   512
#define NH   8
#define HD   64
#define NL   6
#define NF   2048
#define NV   65536
#define NTOK (NB * NS)   // 2048

// ---------------- scratch (device globals; no allocation) ----------------
__device__ float g_x  [NTOK * ND];        // residual stream
__device__ float g_xn [NTOK * ND];        // layernorm output
__device__ float g_qkv[NTOK * 3 * ND];    // qkv projection
__device__ float g_o  [NTOK * ND];        // attention output
__device__ float g_h  [NTOK * NF];        // ffn hidden

// ---------------- tokenize + embed ----------------
// One block per token. proc[16] computed by thread 0 (trivial), then
// x[tok, d] = proc . emb_w[d, :] + emb_b[d].
__global__ void tokenize_embed_kernel(const float* __restrict__ patches,
                                      const float* __restrict__ masked_token,
                                      const float* __restrict__ partial_params,
                                      const float* __restrict__ emb_w,
                                      const float* __restrict__ emb_b) {
    const int tok = blockIdx.x;
    const int tid = threadIdx.x;   // 128 threads
    __shared__ float proc[NP];

    if (tid == 0) {
        const float* f = patches + (size_t)tok * NP;
        bool anyMask = false, anyBin = false;
        int firstBin = -1;
        float fp[NP];
        #pragma unroll
        for (int p = 0; p < NP; p++) {
            float v = f[p];
            fp[p] = v;
            bool m = fabsf(v - 0.5f) < 0.1f;
            if (m) anyMask = true;
            else { anyBin = true; if (firstBin < 0) firstBin = p; }
        }
        if (!anyBin) {                       // fully masked
            #pragma unroll
            for (int p = 0; p < NP; p++) proc[p] = masked_token[p];
        } else if (anyMask) {                // partial
            int ptok = firstBin * 2 + (int)rintf(fp[firstBin]);
            const float* pp = partial_params + ptok * NP;
            #pragma unroll
            for (int p = 0; p < NP; p++) proc[p] = pp[p];
        } else {                             // complete: keep raw values
            #pragma unroll
            for (int p = 0; p < NP; p++) proc[p] = fp[p];
        }
    }
    __syncthreads();

    for (int d = tid; d < ND; d += blockDim.x) {
        const float* w = emb_w + d * NP;
        float s = emb_b[d];
        #pragma unroll
        for (int p = 0; p < NP; p++) s += proc[p] * w[p];
        g_x[(size_t)tok * ND + d] = s;
    }
}

// ---------------- layernorm ----------------
// One block (256 threads) per token; each thread owns 2 features (float2).
__global__ void ln_kernel(const float* __restrict__ in, float* __restrict__ out,
                          const float* __restrict__ gamma, const float* __restrict__ beta) {
    const int tok = blockIdx.x;
    const int tid = threadIdx.x;   // 256
    const float2 v = ((const float2*)(in + (size_t)tok * ND))[tid];

    float s  = v.x + v.y;
    float sq = v.x * v.x + v.y * v.y;
    #pragma unroll
    for (int off = 16; off; off >>= 1) {
        s  += __shfl_xor_sync(0xffffffffu, s,  off);
        sq += __shfl_xor_sync(0xffffffffu, sq, off);
    }
    __shared__ float rs[8], rq[8], stats[2];
    if ((tid & 31) == 0) { rs[tid >> 5] = s; rq[tid >> 5] = sq; }
    __syncthreads();
    if (tid == 0) {
        float S = 0.f, Q = 0.f;
        #pragma unroll
        for (int i = 0; i < 8; i++) { S += rs[i]; Q += rq[i]; }
        float mean = S * (1.0f / ND);
        float var  = Q * (1.0f / ND) - mean * mean;
        stats[0] = mean;
        stats[1] = rsqrtf(var + 1e-5f);
    }
    __syncthreads();
    const float mean = stats[0], inv = stats[1];
    const int d = tid * 2;
    float2 g2 = ((const float2*)gamma)[tid];
    float2 b2 = ((const float2*)beta)[tid];
    float2 o;
    o.x = (v.x - mean) * inv * g2.x + b2.x;
    o.y = (v.y - mean) * inv * g2.y + b2.y;
    ((float2*)(out + (size_t)tok * ND))[tid] = o;
    (void)d;
}

// ---------------- fused attention ----------------
// One block (256 threads) per (b, h, s) query row. Computes 256 scores,
// softmax with max subtraction, then A@V for the 64 head dims.
__global__ void attn_kernel(const float* __restrict__ rel) {
    const int idx = blockIdx.x;
    const int s = idx & (NS - 1);
    const int h = (idx >> 8) & (NH - 1);
    const int b = idx >> 11;
    const int tid = threadIdx.x;   // 256

    __shared__ float q[HD];
    __shared__ float sc[NS];
    __shared__ float redm[8], reds[8], sval[2];
    __shared__ float pv[4][HD];

    const size_t base = (size_t)(b * NS) * (3 * ND) + h * HD;

    if (tid < HD) q[tid] = g_qkv[base + (size_t)s * (3 * ND) + tid];
    __syncthreads();

    // score for key t = tid
    const float* krow = g_qkv + base + ND + (size_t)tid * (3 * ND);
    float dot = 0.f;
    #pragma unroll
    for (int d = 0; d < HD; d += 4) {
        float4 k4 = *(const float4*)(krow + d);
        dot += q[d] * k4.x + q[d + 1] * k4.y + q[d + 2] * k4.z + q[d + 3] * k4.w;
    }
    const float scv = dot * 0.125f + rel[(size_t)s * NS + tid];

    // block max
    float m = scv;
    #pragma unroll
    for (int off = 16; off; off >>= 1) m = fmaxf(m, __shfl_xor_sync(0xffffffffu, m, off));
    if ((tid & 31) == 0) redm[tid >> 5] = m;
    __syncthreads();
    if (tid == 0) {
        float mm = redm[0];
        #pragma unroll
        for (int i = 1; i < 8; i++) mm = fmaxf(mm, redm[i]);
        sval[0] = mm;
    }
    __syncthreads();

    const float e = expf(scv - sval[0]);
    float ss = e;
    #pragma unroll
    for (int off = 16; off; off >>= 1) ss += __shfl_xor_sync(0xffffffffu, ss, off);
    if ((tid & 31) == 0) reds[tid >> 5] = ss;
    __syncthreads();
    if (tid == 0) {
        float t = 0.f;
        #pragma unroll
        for (int i = 0; i < 8; i++) t += reds[i];
        sval[1] = 1.0f / t;
    }
    __syncthreads();
    sc[tid] = e * sval[1];
    __syncthreads();

    // A @ V : 4 groups of 64 keys, 64 dims each
    const int g = tid >> 6, d = tid & 63;
    const float* vcol = g_qkv + base + 2 * ND + d;
    float acc = 0.f;
    const int t0 = g * 64;
    #pragma unroll 8
    for (int t = t0; t < t0 + 64; t++) acc += sc[t] * vcol[(size_t)t * (3 * ND)];
    pv[g][d] = acc;
    __syncthreads();
    if (tid < HD) {
        float o = pv[0][tid] + pv[1][tid] + pv[2][tid] + pv[3][tid];
        g_o[(size_t)(b * NS + s) * ND + h * HD + tid] = o;
    }
}

// ---------------- GEMM: C[M,N] = A[M,K] @ W[N,K]^T + bias (+res) (gelu?) ----
// Classic 128x128x8 SGEMM, 256 threads, 8x8 per thread. M,N mult of 128,
// K mult of 8 (true for all shapes here).
template <bool GELU, bool RES>
__global__ __launch_bounds__(256)
void gemm_kernel(const float* __restrict__ A, const float* __restrict__ W,
                 const float* __restrict__ bias, const float* __restrict__ res,
                 float* __restrict__ C, int M, int N, int K) {
    __shared__ float As[8][128];
    __shared__ float Ws[8][128];

    const int bm = blockIdx.y * 128;
    const int bn = blockIdx.x * 128;
    const int tid = threadIdx.x;

    const int lr = tid >> 1;           // 0..127: row within tile for loading
    const int lk = (tid & 1) * 4;      // 0 or 4: k offset for float4 load
    const int tr = (tid >> 4) * 8;     // output row base within tile
    const int tc = (tid & 15) * 8;     // output col base within tile

    float acc[8][8];
    #pragma unroll
    for (int i = 0; i < 8; i++)
        #pragma unroll
        for (int j = 0; j < 8; j++) acc[i][j] = 0.f;

    const float* aptr = A + (size_t)(bm + lr) * K + lk;
    const float* wptr = W + (size_t)(bn + lr) * K + lk;

    for (int k0 = 0; k0 < K; k0 += 8) {
        float4 a4 = *(const float4*)(aptr + k0);
        float4 w4 = *(const float4*)(wptr + k0);
        As[lk + 0][lr] = a4.x; As[lk + 1][lr] = a4.y;
        As[lk + 2][lr] = a4.z; As[lk + 3][lr] = a4.w;
        Ws[lk + 0][lr] = w4.x; Ws[lk + 1][lr] = w4.y;
        Ws[lk + 2][lr] = w4.z; Ws[lk + 3][lr] = w4.w;
        __syncthreads();

        #pragma unroll
        for (int kk = 0; kk < 8; kk++) {
            float ra[8], rb[8];
            #pragma unroll
            for (int i = 0; i < 8; i++) ra[i] = As[kk][tr + i];
            #pragma unroll
            for (int j = 0; j < 8; j++) rb[j] = Ws[kk][tc + j];
            #pragma unroll
            for (int i = 0; i < 8; i++)
                #pragma unroll
                for (int j = 0; j < 8; j++) acc[i][j] = fmaf(ra[i], rb[j], acc[i][j]);
        }
        __syncthreads();
    }

    // epilogue
    float bv[8];
    #pragma unroll
    for (int j = 0; j < 8; j++) bv[j] = bias[bn + tc + j];

    #pragma unroll
    for (int i = 0; i < 8; i++) {
        const size_t row = (size_t)(bm + tr + i) * N + bn + tc;
        float v[8];
        #pragma unroll
        for (int j = 0; j < 8; j++) {
            float t = acc[i][j] + bv[j];
            if (RES) t += res[row + j];
            if (GELU) t = t * 0.5f * (1.0f + erff(t * 0.70710678118654752f));
            v[j] = t;
        }
        float4* cp = (float4*)(C + row);
        cp[0] = make_float4(v[0], v[1], v[2], v[3]);
        cp[1] = make_float4(v[4], v[5], v[6], v[7]);
    }
}

// ---------------- launch ----------------
extern "C" void kernel_launch(void* const* d_in, const int* in_sizes, int n_in,
                              void* d_out, int out_size) {
    const float* patches       = (const float*)d_in[0];
    // d_in[1] vocab, d_in[2] partial_token_indices: dead in reference output
    const float* masked_token  = (const float*)d_in[3];
    const float* partial_params= (const float*)d_in[4];
    const float* emb_w         = (const float*)d_in[5];
    const float* emb_b         = (const float*)d_in[6];
    const float* ln1_g         = (const float*)d_in[7];
    const float* ln1_b         = (const float*)d_in[8];
    const float* in_proj_w     = (const float*)d_in[9];
    const float* in_proj_b     = (const float*)d_in[10];
    const float* out_proj_w    = (const float*)d_in[11];
    const float* out_proj_b    = (const float*)d_in[12];
    const float* rel_pos       = (const float*)d_in[13];
    const float* ln2_g         = (const float*)d_in[14];
    const float* ln2_b         = (const float*)d_in[15];
    const float* ffn_w1        = (const float*)d_in[16];
    const float* ffn_b1        = (const float*)d_in[17];
    const float* ffn_w2        = (const float*)d_in[18];
    const float* ffn_b2        = (const float*)d_in[19];
    const float* outp_w        = (const float*)d_in[20];
    const float* outp_b        = (const float*)d_in[21];
    float* out = (float*)d_out;

    float *x, *xn, *qkv, *o, *h;
    cudaGetSymbolAddress((void**)&x,   g_x);
    cudaGetSymbolAddress((void**)&xn,  g_xn);
    cudaGetSymbolAddress((void**)&qkv, g_qkv);
    cudaGetSymbolAddress((void**)&o,   g_o);
    cudaGetSymbolAddress((void**)&h,   g_h);

    tokenize_embed_kernel<<<NTOK, 128>>>(patches, masked_token, partial_params, emb_w, emb_b);

    for (int l = 0; l < NL; l++) {
        ln_kernel<<<NTOK, 256>>>(x, xn, ln1_g + l * ND, ln1_b + l * ND);

        gemm_kernel<false, false><<<dim3(3 * ND / 128, NTOK / 128), 256>>>(
            xn, in_proj_w + (size_t)l * 3 * ND * ND, in_proj_b + l * 3 * ND,
            nullptr, qkv, NTOK, 3 * ND, ND);

        attn_kernel<<<NB * NH * NS, 256>>>(rel_pos + (size_t)l * NS * NS);

        gemm_kernel<false, true><<<dim3(ND / 128, NTOK / 128), 256>>>(
            o, out_proj_w + (size_t)l * ND * ND, out_proj_b + l * ND,
            x, x, NTOK, ND, ND);

        ln_kernel<<<NTOK, 256>>>(x, xn, ln2_g + l * ND, ln2_b + l * ND);

        gemm_kernel<true, false><<<dim3(NF / 128, NTOK / 128), 256>>>(
            xn, ffn_w1 + (size_t)l * NF * ND, ffn_b1 + l * NF,
            nullptr, h, NTOK, NF, ND);

        gemm_kernel<false, true><<<dim3(ND / 128, NTOK / 128), 256>>>(
            h, ffn_w2 + (size_t)l * ND * NF, ffn_b2 + l * ND,
            x, x, NTOK, ND, NF);
    }

    gemm_kernel<false, false><<<dim3(NV / 128, NTOK / 128), 256>>>(
        x, outp_w, outp_b, nullptr, out, NTOK, NV, ND);
}

// round 2
// speedup vs baseline: 1.5195x; 1.5195x over previous
#include <cuda_runtime.h>
#include <cuda_bf16.h>
#include <math.h>

// ---------------- problem constants ----------------
#define NB   8
#define NS   256
#define NP   16
#define ND   512
#define NH   8
#define HD   64
#define NL   6
#define NF   2048
#define NV   65536
#define NTOK (NB * NS)   // 2048

// ---------------- scratch (device globals; no allocation) ----------------
__device__ float g_x  [NTOK * ND];        // residual stream
__device__ float g_xn [NTOK * ND];        // layernorm output
__device__ float g_qkv[NTOK * 3 * ND];    // qkv projection
__device__ float g_o  [NTOK * ND];        // attention output
__device__ float g_h  [NTOK * NF];        // ffn hidden

// ---------------- tokenize + embed ----------------
__global__ void tokenize_embed_kernel(const float* __restrict__ patches,
                                      const float* __restrict__ masked_token,
                                      const float* __restrict__ partial_params,
                                      const float* __restrict__ emb_w,
                                      const float* __restrict__ emb_b) {
    const int tok = blockIdx.x;
    const int tid = threadIdx.x;   // 128 threads
    __shared__ float proc[NP];

    if (tid == 0) {
        const float* f = patches + (size_t)tok * NP;
        bool anyMask = false, anyBin = false;
        int firstBin = -1;
        float fp[NP];
        #pragma unroll
        for (int p = 0; p < NP; p++) {
            float v = f[p];
            fp[p] = v;
            bool m = fabsf(v - 0.5f) < 0.1f;
            if (m) anyMask = true;
            else { anyBin = true; if (firstBin < 0) firstBin = p; }
        }
        if (!anyBin) {
            #pragma unroll
            for (int p = 0; p < NP; p++) proc[p] = masked_token[p];
        } else if (anyMask) {
            int ptok = firstBin * 2 + (int)rintf(fp[firstBin]);
            const float* pp = partial_params + ptok * NP;
            #pragma unroll
            for (int p = 0; p < NP; p++) proc[p] = pp[p];
        } else {
            #pragma unroll
            for (int p = 0; p < NP; p++) proc[p] = fp[p];
        }
    }
    __syncthreads();

    for (int d = tid; d < ND; d += blockDim.x) {
        const float* w = emb_w + d * NP;
        float s = emb_b[d];
        #pragma unroll
        for (int p = 0; p < NP; p++) s += proc[p] * w[p];
        g_x[(size_t)tok * ND + d] = s;
    }
}

// ---------------- layernorm ----------------
__global__ void ln_kernel(const float* __restrict__ in, float* __restrict__ out,
                          const float* __restrict__ gamma, const float* __restrict__ beta) {
    const int tok = blockIdx.x;
    const int tid = threadIdx.x;   // 256
    const float2 v = ((const float2*)(in + (size_t)tok * ND))[tid];

    float s  = v.x + v.y;
    float sq = v.x * v.x + v.y * v.y;
    #pragma unroll
    for (int off = 16; off; off >>= 1) {
        s  += __shfl_xor_sync(0xffffffffu, s,  off);
        sq += __shfl_xor_sync(0xffffffffu, sq, off);
    }
    __shared__ float rs[8], rq[8], stats[2];
    if ((tid & 31) == 0) { rs[tid >> 5] = s; rq[tid >> 5] = sq; }
    __syncthreads();
    if (tid == 0) {
        float S = 0.f, Q = 0.f;
        #pragma unroll
        for (int i = 0; i < 8; i++) { S += rs[i]; Q += rq[i]; }
        float mean = S * (1.0f / ND);
        float var  = Q * (1.0f / ND) - mean * mean;
        stats[0] = mean;
        stats[1] = rsqrtf(var + 1e-5f);
    }
    __syncthreads();
    const float mean = stats[0], inv = stats[1];
    float2 g2 = ((const float2*)gamma)[tid];
    float2 b2 = ((const float2*)beta)[tid];
    float2 o;
    o.x = (v.x - mean) * inv * g2.x + b2.x;
    o.y = (v.y - mean) * inv * g2.y + b2.y;
    ((float2*)(out + (size_t)tok * ND))[tid] = o;
}

// ---------------- fused attention ----------------
__global__ void attn_kernel(const float* __restrict__ rel) {
    const int idx = blockIdx.x;
    const int s = idx & (NS - 1);
    const int h = (idx >> 8) & (NH - 1);
    const int b = idx >> 11;
    const int tid = threadIdx.x;   // 256

    __shared__ float q[HD];
    __shared__ float sc[NS];
    __shared__ float redm[8], reds[8], sval[2];
    __shared__ float pv[4][HD];

    const size_t base = (size_t)(b * NS) * (3 * ND) + h * HD;

    if (tid < HD) q[tid] = g_qkv[base + (size_t)s * (3 * ND) + tid];
    __syncthreads();

    const float* krow = g_qkv + base + ND + (size_t)tid * (3 * ND);
    float dot = 0.f;
    #pragma unroll
    for (int d = 0; d < HD; d += 4) {
        float4 k4 = *(const float4*)(krow + d);
        dot += q[d] * k4.x + q[d + 1] * k4.y + q[d + 2] * k4.z + q[d + 3] * k4.w;
    }
    const float scv = dot * 0.125f + rel[(size_t)s * NS + tid];

    float m = scv;
    #pragma unroll
    for (int off = 16; off; off >>= 1) m = fmaxf(m, __shfl_xor_sync(0xffffffffu, m, off));
    if ((tid & 31) == 0) redm[tid >> 5] = m;
    __syncthreads();
    if (tid == 0) {
        float mm = redm[0];
        #pragma unroll
        for (int i = 1; i < 8; i++) mm = fmaxf(mm, redm[i]);
        sval[0] = mm;
    }
    __syncthreads();

    const float e = expf(scv - sval[0]);
    float ss = e;
    #pragma unroll
    for (int off = 16; off; off >>= 1) ss += __shfl_xor_sync(0xffffffffu, ss, off);
    if ((tid & 31) == 0) reds[tid >> 5] = ss;
    __syncthreads();
    if (tid == 0) {
        float tt = 0.f;
        #pragma unroll
        for (int i = 0; i < 8; i++) tt += reds[i];
        sval[1] = 1.0f / tt;
    }
    __syncthreads();
    sc[tid] = e * sval[1];
    __syncthreads();

    const int g = tid >> 6, d = tid & 63;
    const float* vcol = g_qkv + base + 2 * ND + d;
    float acc = 0.f;
    const int t0 = g * 64;
    #pragma unroll 8
    for (int t = t0; t < t0 + 64; t++) acc += sc[t] * vcol[(size_t)t * (3 * ND)];
    pv[g][d] = acc;
    __syncthreads();
    if (tid < HD) {
        float o = pv[0][tid] + pv[1][tid] + pv[2][tid] + pv[3][tid];
        g_o[(size_t)(b * NS + s) * ND + h * HD + tid] = o;
    }
}

// ---------------- TF32 tensor-core GEMM ----------------
// C[M,N] = A[M,K] @ W[N,K]^T + bias (+res) (gelu?)
// 128x128x16 block tile, 256 threads = 8 warps (2x4), warp tile 64x32,
// per warp 4x4 fragments of mma.m16n8k8.tf32. fp32 accumulate.
__device__ __forceinline__ float f2tf(float x) {
    unsigned y;
    asm("cvt.rna.tf32.f32 %0, %1;" : "=r"(y) : "f"(x));
    return __uint_as_float(y);
}

#define SST 132   // smem row stride (floats): bank = (4k+m) mod 32 conflict-free

template <bool GELU, bool RES>
__global__ __launch_bounds__(256)
void gemm_tf32(const float* __restrict__ A, const float* __restrict__ W,
               const float* __restrict__ bias, const float* __restrict__ res,
               float* __restrict__ C, int M, int N, int K) {
    __shared__ float As[16][SST];
    __shared__ float Ws[16][SST];

    const int tid = threadIdx.x;
    const int bm = blockIdx.y * 128;
    const int bn = blockIdx.x * 128;

    const int lr = tid & 127;          // row within tile for global load
    const int kq = (tid >> 7) * 4;     // 0 or 4 (second chunk at +8)

    const int wid = tid >> 5, lane = tid & 31;
    const int g = lane >> 2, t = lane & 3;
    const int wm = (wid >> 2) * 64;    // warp row base (0/64)
    const int wn = (wid & 3) * 32;     // warp col base (0/32/64/96)

    float acc[4][4][4];
    #pragma unroll
    for (int i = 0; i < 4; i++)
        #pragma unroll
        for (int j = 0; j < 4; j++)
            #pragma unroll
            for (int c = 0; c < 4; c++) acc[i][j][c] = 0.f;

    const float* aP = A + (size_t)(bm + lr) * K + kq;
    const float* wP = W + (size_t)(bn + lr) * K + kq;

    float4 a0v = *(const float4*)(aP);
    float4 a1v = *(const float4*)(aP + 8);
    float4 w0v = *(const float4*)(wP);
    float4 w1v = *(const float4*)(wP + 8);

    for (int k0 = 0; k0 < K; k0 += 16) {
        As[kq + 0][lr] = f2tf(a0v.x); As[kq + 1][lr] = f2tf(a0v.y);
        As[kq + 2][lr] = f2tf(a0v.z); As[kq + 3][lr] = f2tf(a0v.w);
        As[kq + 8][lr] = f2tf(a1v.x); As[kq + 9][lr] = f2tf(a1v.y);
        As[kq +10][lr] = f2tf(a1v.z); As[kq +11][lr] = f2tf(a1v.w);
        Ws[kq + 0][lr] = f2tf(w0v.x); Ws[kq + 1][lr] = f2tf(w0v.y);
        Ws[kq + 2][lr] = f2tf(w0v.z); Ws[kq + 3][lr] = f2tf(w0v.w);
        Ws[kq + 8][lr] = f2tf(w1v.x); Ws[kq + 9][lr] = f2tf(w1v.y);
        Ws[kq +10][lr] = f2tf(w1v.z); Ws[kq +11][lr] = f2tf(w1v.w);
        __syncthreads();

        if (k0 + 16 < K) {   // prefetch next tile while computing
            a0v = *(const float4*)(aP + k0 + 16);
            a1v = *(const float4*)(aP + k0 + 24);
            w0v = *(const float4*)(wP + k0 + 16);
            w1v = *(const float4*)(wP + k0 + 24);
        }

        #pragma unroll
        for (int ks = 0; ks < 16; ks += 8) {
            unsigned af[4][4], bf[4][2];
            #pragma unroll
            for (int mf = 0; mf < 4; mf++) {
                const int r0 = wm + mf * 16 + g;
                af[mf][0] = __float_as_uint(As[ks + t][r0]);
                af[mf][1] = __float_as_uint(As[ks + t][r0 + 8]);
                af[mf][2] = __float_as_uint(As[ks + t + 4][r0]);
                af[mf][3] = __float_as_uint(As[ks + t + 4][r0 + 8]);
            }
            #pragma unroll
            for (int nf = 0; nf < 4; nf++) {
                const int c0 = wn + nf * 8 + g;
                bf[nf][0] = __float_as_uint(Ws[ks + t][c0]);
                bf[nf][1] = __float_as_uint(Ws[ks + t + 4][c0]);
            }
            #pragma unroll
            for (int mf = 0; mf < 4; mf++)
                #pragma unroll
                for (int nf = 0; nf < 4; nf++) {
                    asm volatile(
                        "mma.sync.aligned.m16n8k8.row.col.f32.tf32.tf32.f32 "
                        "{%0,%1,%2,%3}, {%4,%5,%6,%7}, {%8,%9}, {%0,%1,%2,%3};"
                        : "+f"(acc[mf][nf][0]), "+f"(acc[mf][nf][1]),
                          "+f"(acc[mf][nf][2]), "+f"(acc[mf][nf][3])
                        : "r"(af[mf][0]), "r"(af[mf][1]), "r"(af[mf][2]), "r"(af[mf][3]),
                          "r"(bf[nf][0]), "r"(bf[nf][1]));
                }
        }
        __syncthreads();
    }

    // epilogue
    #pragma unroll
    for (int mf = 0; mf < 4; mf++) {
        const int r0 = bm + wm + mf * 16 + g;
        #pragma unroll
        for (int nf = 0; nf < 4; nf++) {
            const int c0 = bn + wn + nf * 8 + 2 * t;
            const float2 bv = *(const float2*)(bias + c0);
            float v00 = acc[mf][nf][0] + bv.x;
            float v01 = acc[mf][nf][1] + bv.y;
            float v10 = acc[mf][nf][2] + bv.x;
            float v11 = acc[mf][nf][3] + bv.y;
            const size_t i0 = (size_t)r0 * N + c0;
            const size_t i1 = (size_t)(r0 + 8) * N + c0;
            if (RES) {
                const float2 r0v = *(const float2*)(res + i0);
                const float2 r1v = *(const float2*)(res + i1);
                v00 += r0v.x; v01 += r0v.y; v10 += r1v.x; v11 += r1v.y;
            }
            if (GELU) {
                v00 = v00 * 0.5f * (1.0f + erff(v00 * 0.70710678118654752f));
                v01 = v01 * 0.5f * (1.0f + erff(v01 * 0.70710678118654752f));
                v10 = v10 * 0.5f * (1.0f + erff(v10 * 0.70710678118654752f));
                v11 = v11 * 0.5f * (1.0f + erff(v11 * 0.70710678118654752f));
            }
            *(float2*)(C + i0) = make_float2(v00, v01);
            *(float2*)(C + i1) = make_float2(v10, v11);
        }
    }
}

// ---------------- launch ----------------
extern "C" void kernel_launch(void* const* d_in, const int* in_sizes, int n_in,
                              void* d_out, int out_size) {
    const float* patches        = (const float*)d_in[0];
    const float* masked_token   = (const float*)d_in[3];
    const float* partial_params = (const float*)d_in[4];
    const float* emb_w          = (const float*)d_in[5];
    const float* emb_b          = (const float*)d_in[6];
    const float* ln1_g          = (const float*)d_in[7];
    const float* ln1_b          = (const float*)d_in[8];
    const float* in_proj_w      = (const float*)d_in[9];
    const float* in_proj_b      = (const float*)d_in[10];
    const float* out_proj_w     = (const float*)d_in[11];
    const float* out_proj_b     = (const float*)d_in[12];
    const float* rel_pos        = (const float*)d_in[13];
    const float* ln2_g          = (const float*)d_in[14];
    const float* ln2_b          = (const float*)d_in[15];
    const float* ffn_w1         = (const float*)d_in[16];
    const float* ffn_b1         = (const float*)d_in[17];
    const float* ffn_w2         = (const float*)d_in[18];
    const float* ffn_b2         = (const float*)d_in[19];
    const float* outp_w         = (const float*)d_in[20];
    const float* outp_b         = (const float*)d_in[21];
    float* out = (float*)d_out;

    float *x, *xn, *qkv, *o, *h;
    cudaGetSymbolAddress((void**)&x,   g_x);
    cudaGetSymbolAddress((void**)&xn,  g_xn);
    cudaGetSymbolAddress((void**)&qkv, g_qkv);
    cudaGetSymbolAddress((void**)&o,   g_o);
    cudaGetSymbolAddress((void**)&h,   g_h);

    tokenize_embed_kernel<<<NTOK, 128>>>(patches, masked_token, partial_params, emb_w, emb_b);

    for (int l = 0; l < NL; l++) {
        ln_kernel<<<NTOK, 256>>>(x, xn, ln1_g + l * ND, ln1_b + l * ND);

        gemm_tf32<false, false><<<dim3(3 * ND / 128, NTOK / 128), 256>>>(
            xn, in_proj_w + (size_t)l * 3 * ND * ND, in_proj_b + l * 3 * ND,
            nullptr, qkv, NTOK, 3 * ND, ND);

        attn_kernel<<<NB * NH * NS, 256>>>(rel_pos + (size_t)l * NS * NS);

        gemm_tf32<false, true><<<dim3(ND / 128, NTOK / 128), 256>>>(
            o, out_proj_w + (size_t)l * ND * ND, out_proj_b + l * ND,
            x, x, NTOK, ND, ND);

        ln_kernel<<<NTOK, 256>>>(x, xn, ln2_g + l * ND, ln2_b + l * ND);

        gemm_tf32<true, false><<<dim3(NF / 128, NTOK / 128), 256>>>(
            xn, ffn_w1 + (size_t)l * NF * ND, ffn_b1 + l * NF,
            nullptr, h, NTOK, NF, ND);

        gemm_tf32<false, true><<<dim3(ND / 128, NTOK / 128), 256>>>(
            h, ffn_w2 + (size_t)l * ND * NF, ffn_b2 + l * ND,
            x, x, NTOK, ND, NF);
    }

    gemm_tf32<false, false><<<dim3(NV / 128, NTOK / 128), 256>>>(
        x, outp_w, outp_b, nullptr, out, NTOK, NV, ND);
}